// round 10
// baseline (speedup 1.0000x reference)
#include <cuda_runtime.h>
#include <cstdint>

#define BATCH 8192
#define K_IN  1024
#define NDIM  2048
#define TWO_N 4096

// Device-global scratch (allocation-free rule):
//  g_mul: inputs_mul result (128 MB)
//  g_a  : tf32-rounded + k-permuted inputs  (32 MB)
//  g_w  : tf32-rounded + k-permuted w_ih    (16 MB)
__device__ float g_mul[(size_t)BATCH * TWO_N];
__device__ float g_a[(size_t)BATCH * K_IN];
__device__ float g_w[(size_t)TWO_N * K_IN];

// ============================================================================
// Prep: dst[j] = tf32_rna(src[depermute(j)]), permute within each 8-col group
// to [0,4,1,5,2,6,3,7] so mma fragment pairs (t, t+4) are adjacent in smem.
// ============================================================================
__global__ __launch_bounds__(256) void prep_tf32_kernel(
    const float* __restrict__ src, float* __restrict__ dst, int n)
{
    int j = (blockIdx.x * 256 + threadIdx.x) * 4;
    if (j >= n) return;
    #pragma unroll
    for (int u = 0; u < 4; ++u) {
        const int jj = j + u;
        const int grp = jj & ~7;
        const int r   = jj & 7;
        const int c   = (r >> 1) + ((r & 1) ? 4 : 0);
        uint32_t b;
        asm("cvt.rna.tf32.f32 %0, %1;" : "=r"(b) : "f"(src[grp + c]));
        dst[jj] = __uint_as_float(b);
    }
}

// ============================================================================
// GEMM: C[8192,4096] = A[8192,1024] * W[4096,1024]^T
// tf32 mma.sync, fp32 accum. Inputs pre-rounded+permuted -> no CVT in loop,
// fragment loads are LDS.64.
// ============================================================================
#define BM 128
#define BN 128
#define BK 16
#define NIT (K_IN / BK)   // 64

__device__ __forceinline__ void cp16(void* dst_smem, const void* src) {
    uint32_t d = (uint32_t)__cvta_generic_to_shared(dst_smem);
    asm volatile("cp.async.cg.shared.global [%0], [%1], 16;" :: "r"(d), "l"(src) : "memory");
}

__device__ __forceinline__ void mma_tf32(float* c, const uint32_t* a, const uint32_t* b) {
    asm volatile(
        "mma.sync.aligned.m16n8k8.row.col.f32.tf32.tf32.f32 "
        "{%0,%1,%2,%3}, {%4,%5,%6,%7}, {%8,%9}, {%0,%1,%2,%3};\n"
        : "+f"(c[0]), "+f"(c[1]), "+f"(c[2]), "+f"(c[3])
        : "r"(a[0]), "r"(a[1]), "r"(a[2]), "r"(a[3]), "r"(b[0]), "r"(b[1]));
}

__global__ __launch_bounds__(256) void gemm_tf32_kernel(
    const float* __restrict__ A, const float* __restrict__ W)
{
    __shared__ float As[2][BM][BK + 4];
    __shared__ float Bs[2][BN][BK + 4];

    const int tid  = threadIdx.x;
    const int warp = tid >> 5, lane = tid & 31;
    const int g = lane >> 2, t = lane & 3;
    const int tcol = 2 * t;           // permuted position of (t, t+4) pair
    const int wm = (warp & 1) * 64;   // warp tile 64(M) x 32(N), 2x4 warp grid
    const int wn = (warp >> 1) * 32;
    const int bm = blockIdx.y * BM;
    const int bn = blockIdx.x * BN;

    const int lr = tid >> 2;          // 0..63 -> rows lr, lr+64
    const int lc = (tid & 3) * 4;     // k offset 0,4,8,12

    float acc[4][4][4];
    #pragma unroll
    for (int mi = 0; mi < 4; ++mi)
        #pragma unroll
        for (int ni = 0; ni < 4; ++ni)
            #pragma unroll
            for (int r = 0; r < 4; ++r) acc[mi][ni][r] = 0.0f;

    // prologue: stage 0
    {
        const float* a0 = A + (size_t)(bm + lr) * K_IN + lc;
        const float* b0 = W + (size_t)(bn + lr) * K_IN + lc;
        cp16(&As[0][lr][lc],      a0);
        cp16(&As[0][lr + 64][lc], a0 + (size_t)64 * K_IN);
        cp16(&Bs[0][lr][lc],      b0);
        cp16(&Bs[0][lr + 64][lc], b0 + (size_t)64 * K_IN);
        asm volatile("cp.async.commit_group;");
    }

    for (int it = 0; it < NIT; ++it) {
        asm volatile("cp.async.wait_group 0;");
        __syncthreads();

        if (it + 1 < NIT) {
            const int k0 = (it + 1) * BK;
            const int ns = (it + 1) & 1;
            const float* a0 = A + (size_t)(bm + lr) * K_IN + k0 + lc;
            const float* b0 = W + (size_t)(bn + lr) * K_IN + k0 + lc;
            cp16(&As[ns][lr][lc],      a0);
            cp16(&As[ns][lr + 64][lc], a0 + (size_t)64 * K_IN);
            cp16(&Bs[ns][lr][lc],      b0);
            cp16(&Bs[ns][lr + 64][lc], b0 + (size_t)64 * K_IN);
            asm volatile("cp.async.commit_group;");
        }

        const int s = it & 1;
        #pragma unroll
        for (int kk = 0; kk < BK; kk += 8) {
            uint32_t af[4][4], bf[4][2];
            #pragma unroll
            for (int mi = 0; mi < 4; ++mi) {
                const int m = wm + mi * 16 + g;
                const float2 x = *(const float2*)&As[s][m][kk + tcol];      // (t, t+4)
                const float2 y = *(const float2*)&As[s][m + 8][kk + tcol];
                af[mi][0] = __float_as_uint(x.x);
                af[mi][2] = __float_as_uint(x.y);
                af[mi][1] = __float_as_uint(y.x);
                af[mi][3] = __float_as_uint(y.y);
            }
            #pragma unroll
            for (int ni = 0; ni < 4; ++ni) {
                const int n = wn + ni * 8 + g;
                const float2 z = *(const float2*)&Bs[s][n][kk + tcol];
                bf[ni][0] = __float_as_uint(z.x);
                bf[ni][1] = __float_as_uint(z.y);
            }
            #pragma unroll
            for (int mi = 0; mi < 4; ++mi)
                #pragma unroll
                for (int ni = 0; ni < 4; ++ni)
                    mma_tf32(acc[mi][ni], af[mi], bf[ni]);
        }
    }

    #pragma unroll
    for (int mi = 0; mi < 4; ++mi)
        #pragma unroll
        for (int ni = 0; ni < 4; ++ni) {
            const int m = bm + wm + mi * 16 + g;
            const int n = bn + wn + ni * 8 + 2 * t;
            float2 v0 = make_float2(acc[mi][ni][0], acc[mi][ni][1]);
            float2 v1 = make_float2(acc[mi][ni][2], acc[mi][ni][3]);
            *(float2*)&g_mul[(size_t)m * TWO_N + n]       = v0;
            *(float2*)&g_mul[(size_t)(m + 8) * TWO_N + n] = v1;
        }
}

// ============================================================================
// Fused per-row URNN, mixed-radix 8*8*8*4 register FFT. (unchanged from R6)
// ============================================================================
#define RT  256
#define SW(i) ((i) ^ (((i) >> 3) & 31))
#define FPI 3.14159265358979f

__device__ __forceinline__ void bfly(float& ar, float& ai, float& br, float& bi,
                                     float wr, float wi)
{
    const float tr = wr * br - wi * bi;
    const float ti = wr * bi + wi * br;
    br = ar - tr; bi = ai - ti;
    ar = ar + tr; ai = ai + ti;
}

__device__ __forceinline__ void radix8(float* xr, float* xi, float phi, float sgn)
{
    float c1, s1, c2, s2, c3, s3;
    __sincosf(phi,          &s1, &c1);
    __sincosf(phi * 0.50f,  &s2, &c2);
    __sincosf(phi * 0.25f,  &s3, &c3);
    bfly(xr[0], xi[0], xr[1], xi[1], c1, s1);
    bfly(xr[2], xi[2], xr[3], xi[3], c1, s1);
    bfly(xr[4], xi[4], xr[5], xi[5], c1, s1);
    bfly(xr[6], xi[6], xr[7], xi[7], c1, s1);
    const float wbr = -sgn * s2, wbi = sgn * c2;
    bfly(xr[0], xi[0], xr[2], xi[2], c2, s2);
    bfly(xr[1], xi[1], xr[3], xi[3], wbr, wbi);
    bfly(xr[4], xi[4], xr[6], xi[6], c2, s2);
    bfly(xr[5], xi[5], xr[7], xi[7], wbr, wbi);
    const float h = 0.70710678118f;
    const float w1r = h * (c3 - sgn * s3), w1i = h * (sgn * c3 + s3);
    const float w2r = -sgn * s3,           w2i = sgn * c3;
    const float w3r = -h * (c3 + sgn * s3), w3i = h * (sgn * c3 - s3);
    bfly(xr[0], xi[0], xr[4], xi[4], c3, s3);
    bfly(xr[1], xi[1], xr[5], xi[5], w1r, w1i);
    bfly(xr[2], xi[2], xr[6], xi[6], w2r, w2i);
    bfly(xr[3], xi[3], xr[7], xi[7], w3r, w3i);
}

__device__ __forceinline__ void radix4(float* xr, float* xi, float alpha, float sgn)
{
    float c1, s1, c2, s2;
    __sincosf(alpha,         &s1, &c1);
    __sincosf(alpha * 0.5f,  &s2, &c2);
    bfly(xr[0], xi[0], xr[1], xi[1], c1, s1);
    bfly(xr[2], xi[2], xr[3], xi[3], c1, s1);
    const float wbr = -sgn * s2, wbi = sgn * c2;
    bfly(xr[0], xi[0], xr[2], xi[2], c2, s2);
    bfly(xr[1], xi[1], xr[3], xi[3], wbr, wbi);
}

__device__ __forceinline__ void fft2048_r8(float* __restrict__ sre, float* __restrict__ sim,
                                           int tid, float sgn, float* zr, float* zi)
{
    float xr[8], xi[8];
    const int rT = (int)(__brev((unsigned)tid) >> 24);   // rev8(tid)
    #pragma unroll
    for (int e = 0; e < 8; ++e) {
        const int r3 = ((e & 1) << 2) | (e & 2) | ((e & 4) >> 2);   // rev3(e)
        const int a = SW((r3 << 8) | rT);
        xr[e] = sre[a]; xi[e] = sim[a];
    }
    __syncthreads();
    radix8(xr, xi, 0.0f, sgn);
    #pragma unroll
    for (int e = 0; e < 8; ++e) {
        const int a = SW(8 * tid + e);
        sre[a] = xr[e]; sim[a] = xi[e];
    }
    __syncthreads();
    {
        const int low = tid & 7, base = ((tid >> 3) << 6) + low;
        #pragma unroll
        for (int e = 0; e < 8; ++e) { const int a = SW(base + 8 * e); xr[e] = sre[a]; xi[e] = sim[a]; }
        radix8(xr, xi, sgn * FPI * (float)low * 0.125f, sgn);
        #pragma unroll
        for (int e = 0; e < 8; ++e) { const int a = SW(base + 8 * e); sre[a] = xr[e]; sim[a] = xi[e]; }
    }
    __syncthreads();
    {
        const int low = tid & 63, base = ((tid >> 6) << 9) + low;
        #pragma unroll
        for (int e = 0; e < 8; ++e) { const int a = SW(base + 64 * e); xr[e] = sre[a]; xi[e] = sim[a]; }
        radix8(xr, xi, sgn * FPI * (float)low * (1.0f / 64.0f), sgn);
        #pragma unroll
        for (int e = 0; e < 8; ++e) { const int a = SW(base + 64 * e); sre[a] = xr[e]; sim[a] = xi[e]; }
    }
    __syncthreads();
    #pragma unroll
    for (int r = 0; r < 2; ++r) {
        const int low = tid + 256 * r;
        float br[4], bi[4];
        #pragma unroll
        for (int e = 0; e < 4; ++e) { const int a = SW(low + 512 * e); br[e] = sre[a]; bi[e] = sim[a]; }
        radix4(br, bi, sgn * FPI * (float)low * (1.0f / 512.0f), sgn);
        #pragma unroll
        for (int e = 0; e < 4; ++e) { zr[r * 4 + e] = br[e]; zi[r * 4 + e] = bi[e]; }
    }
}

__device__ __forceinline__ void reflect_regs(float* zr, float* zi,
    const float* __restrict__ vre, const float* __restrict__ vim,
    float* red, int tid)
{
    float sq = 0.f, dr = 0.f, di = 0.f;
    #pragma unroll
    for (int r = 0; r < 2; ++r)
        #pragma unroll
        for (int e = 0; e < 4; ++e) {
            const int i = tid + 256 * r + 512 * e;
            const float vr = vre[i], vi = vim[i];
            const float a = zr[r * 4 + e], b = zi[r * 4 + e];
            sq += vr * vr + vi * vi;
            dr += a * vr + b * vi;
            di += b * vr - a * vi;
        }
    #pragma unroll
    for (int off = 16; off > 0; off >>= 1) {
        sq += __shfl_down_sync(0xffffffffu, sq, off);
        dr += __shfl_down_sync(0xffffffffu, dr, off);
        di += __shfl_down_sync(0xffffffffu, di, off);
    }
    const int warp = tid >> 5, lane = tid & 31;
    if (lane == 0) { red[warp] = sq; red[8 + warp] = dr; red[16 + warp] = di; }
    __syncthreads();
    if (tid == 0) {
        float a = 0.f, b = 0.f, c = 0.f;
        #pragma unroll
        for (int w = 0; w < 8; ++w) { a += red[w]; b += red[8 + w]; c += red[16 + w]; }
        const float f = 2.0f / a;
        red[24] = f * b;
        red[25] = f * c;
    }
    __syncthreads();
    const float cr = red[24], ci = red[25];
    #pragma unroll
    for (int r = 0; r < 2; ++r)
        #pragma unroll
        for (int e = 0; e < 4; ++e) {
            const int i = tid + 256 * r + 512 * e;
            const float vr = vre[i], vi = vim[i];
            zr[r * 4 + e] -= cr * vr - ci * vi;
            zi[r * 4 + e] -= cr * vi + ci * vr;
        }
}

__global__ __launch_bounds__(RT, 2) void urnn_row_kernel(
    const float* __restrict__ state,
    const float* __restrict__ b_h,
    const float* __restrict__ d1, const float* __restrict__ r1re, const float* __restrict__ r1im,
    const float* __restrict__ d2, const float* __restrict__ r2re, const float* __restrict__ r2im,
    const float* __restrict__ d3, const int* __restrict__ perm,
    float* __restrict__ out)
{
    __shared__ float sre[NDIM], sim[NDIM];
    __shared__ float red[32];

    const int tid = threadIdx.x;
    const size_t row = (size_t)blockIdx.x * TWO_N;
    const float* st   = state + row;
    const float* mrow = g_mul + row;
    float*       orow = out + row;

    float zr[8], zi[8];

    #pragma unroll
    for (int j = 0; j < 8; ++j) {
        const int i = tid + j * RT;
        const float re = st[i], im = st[i + NDIM];
        float c, s;
        __sincosf(d1[i], &s, &c);
        const int a = SW(i);
        sre[a] = c * re - s * im;
        sim[a] = c * im + s * re;
    }
    __syncthreads();

    fft2048_r8(sre, sim, tid, -1.0f, zr, zi);
    reflect_regs(zr, zi, r1re, r1im, red, tid);

    #pragma unroll
    for (int r = 0; r < 2; ++r)
        #pragma unroll
        for (int e = 0; e < 4; ++e) {
            const int i = tid + 256 * r + 512 * e;
            const int a = SW(i);
            sre[a] = zr[r * 4 + e]; sim[a] = zi[r * 4 + e];
        }
    __syncthreads();

    {
        float tre[8], tim[8];
        #pragma unroll
        for (int j = 0; j < 8; ++j) {
            const int i = tid + j * RT;
            const int p = perm[i];
            const int a = SW(p);
            tre[j] = sre[a]; tim[j] = sim[a];
        }
        __syncthreads();
        #pragma unroll
        for (int j = 0; j < 8; ++j) {
            const int i = tid + j * RT;
            float c, s;
            __sincosf(d2[i], &s, &c);
            const int a = SW(i);
            sre[a] = c * tre[j] - s * tim[j];
            sim[a] = c * tim[j] + s * tre[j];
        }
        __syncthreads();
    }

    fft2048_r8(sre, sim, tid, +1.0f, zr, zi);
    reflect_regs(zr, zi, r2re, r2im, red, tid);

    const float invn = 1.0f / (float)NDIM;
    #pragma unroll
    for (int r = 0; r < 2; ++r)
        #pragma unroll
        for (int e = 0; e < 4; ++e) {
            const int i = tid + 256 * r + 512 * e;
            const float zr0 = zr[r * 4 + e], zi0 = zi[r * 4 + e];
            float c, s;
            __sincosf(d3[i], &s, &c);
            const float zzr = (c * zr0 - s * zi0) * invn;
            const float zzi = (c * zi0 + s * zr0) * invn;
            const float pr = mrow[i] + zzr;
            const float pi = mrow[i + NDIM] + zzi;
            const float nrm = sqrtf(pr * pr + pi * pi);
            const float sc = fmaxf(nrm + b_h[i], 0.0f) / (nrm + 1e-6f);
            orow[i]        = pr * sc;
            orow[i + NDIM] = pi * sc;
        }
}

// ============================================================================
extern "C" void kernel_launch(void* const* d_in, const int* in_sizes, int n_in,
                              void* d_out, int out_size)
{
    const float* inputs = (const float*)d_in[0];
    const float* state  = (const float*)d_in[1];
    const float* w_ih   = (const float*)d_in[2];
    const float* b_h    = (const float*)d_in[3];
    const float* d1     = (const float*)d_in[4];
    const float* r1re   = (const float*)d_in[5];
    const float* r1im   = (const float*)d_in[6];
    const float* d2     = (const float*)d_in[7];
    const float* r2re   = (const float*)d_in[8];
    const float* r2im   = (const float*)d_in[9];
    const float* d3     = (const float*)d_in[10];
    const int*   perm   = (const int*)d_in[11];
    float* out = (float*)d_out;

    float* ga; cudaGetSymbolAddress((void**)&ga, g_a);
    float* gw; cudaGetSymbolAddress((void**)&gw, g_w);

    const int nA = BATCH * K_IN;     // 8M
    const int nW = TWO_N * K_IN;     // 4M
    prep_tf32_kernel<<<nA / 1024, 256>>>(inputs, ga, nA);
    prep_tf32_kernel<<<nW / 1024, 256>>>(w_ih,   gw, nW);

    dim3 ggrid(TWO_N / BN, BATCH / BM);       // (32, 64)
    gemm_tf32_kernel<<<ggrid, 256>>>(ga, gw);
    urnn_row_kernel<<<BATCH, RT>>>(state, b_h, d1, r1re, r1im,
                                   d2, r2re, r2im, d3, perm, out);
}

// round 13
// speedup vs baseline: 1.0588x; 1.0588x over previous
#include <cuda_runtime.h>
#include <cstdint>

#define BATCH 8192
#define K_IN  1024
#define NDIM  2048
#define TWO_N 4096

// 128 MB scratch for inputs_mul = inputs @ w_ih^T  (allocation-free rule: device global)
__device__ float g_mul[(size_t)BATCH * TWO_N];

// ============================================================================
// GEMM: C[8192,4096] = A[8192,1024] * W[4096,1024]^T   (tf32 mma.sync, fp32 accum)
// __launch_bounds__(256, 2): cap regs at 128 so 2 CTAs/SM co-reside
// (4 warps/SMSP to hide LDS latency behind the 25%-density MMA stream).
// ============================================================================
#define BM 128
#define BN 128
#define BK 16
#define NIT (K_IN / BK)   // 64

__device__ __forceinline__ uint32_t f2tf32(float x) {
    uint32_t r;
    asm("cvt.rna.tf32.f32 %0, %1;" : "=r"(r) : "f"(x));
    return r;
}

__device__ __forceinline__ void cp16(void* dst_smem, const void* src) {
    uint32_t d = (uint32_t)__cvta_generic_to_shared(dst_smem);
    asm volatile("cp.async.cg.shared.global [%0], [%1], 16;" :: "r"(d), "l"(src) : "memory");
}

__device__ __forceinline__ void mma_tf32(float* c, const uint32_t* a, const uint32_t* b) {
    asm volatile(
        "mma.sync.aligned.m16n8k8.row.col.f32.tf32.tf32.f32 "
        "{%0,%1,%2,%3}, {%4,%5,%6,%7}, {%8,%9}, {%0,%1,%2,%3};\n"
        : "+f"(c[0]), "+f"(c[1]), "+f"(c[2]), "+f"(c[3])
        : "r"(a[0]), "r"(a[1]), "r"(a[2]), "r"(a[3]), "r"(b[0]), "r"(b[1]));
}

__global__ __launch_bounds__(256, 2) void gemm_tf32_kernel(
    const float* __restrict__ A, const float* __restrict__ W)
{
    __shared__ float As[2][BM][BK + 4];
    __shared__ float Bs[2][BN][BK + 4];

    const int tid  = threadIdx.x;
    const int warp = tid >> 5, lane = tid & 31;
    const int g = lane >> 2, t = lane & 3;
    const int wm = (warp & 1) * 64;   // warp tile 64(M) x 32(N), 2x4 warp grid
    const int wn = (warp >> 1) * 32;
    const int bm = blockIdx.y * BM;
    const int bn = blockIdx.x * BN;

    const int lr = tid >> 2;          // 0..63 -> rows lr, lr+64
    const int lc = (tid & 3) * 4;     // k offset 0,4,8,12

    float acc[4][4][4];
    #pragma unroll
    for (int mi = 0; mi < 4; ++mi)
        #pragma unroll
        for (int ni = 0; ni < 4; ++ni)
            #pragma unroll
            for (int r = 0; r < 4; ++r) acc[mi][ni][r] = 0.0f;

    // prologue: stage 0
    {
        const float* a0 = A + (size_t)(bm + lr) * K_IN + lc;
        const float* b0 = W + (size_t)(bn + lr) * K_IN + lc;
        cp16(&As[0][lr][lc],      a0);
        cp16(&As[0][lr + 64][lc], a0 + (size_t)64 * K_IN);
        cp16(&Bs[0][lr][lc],      b0);
        cp16(&Bs[0][lr + 64][lc], b0 + (size_t)64 * K_IN);
        asm volatile("cp.async.commit_group;");
    }

    for (int it = 0; it < NIT; ++it) {
        asm volatile("cp.async.wait_group 0;");
        __syncthreads();                       // single barrier per iteration

        if (it + 1 < NIT) {
            const int k0 = (it + 1) * BK;
            const int ns = (it + 1) & 1;
            const float* a0 = A + (size_t)(bm + lr) * K_IN + k0 + lc;
            const float* b0 = W + (size_t)(bn + lr) * K_IN + k0 + lc;
            cp16(&As[ns][lr][lc],      a0);
            cp16(&As[ns][lr + 64][lc], a0 + (size_t)64 * K_IN);
            cp16(&Bs[ns][lr][lc],      b0);
            cp16(&Bs[ns][lr + 64][lc], b0 + (size_t)64 * K_IN);
            asm volatile("cp.async.commit_group;");
        }

        const int s = it & 1;
        #pragma unroll
        for (int kk = 0; kk < BK; kk += 8) {
            uint32_t af[4][4], bf[4][2];
            #pragma unroll
            for (int mi = 0; mi < 4; ++mi) {
                const int m = wm + mi * 16 + g;
                af[mi][0] = f2tf32(As[s][m][kk + t]);
                af[mi][1] = f2tf32(As[s][m + 8][kk + t]);
                af[mi][2] = f2tf32(As[s][m][kk + t + 4]);
                af[mi][3] = f2tf32(As[s][m + 8][kk + t + 4]);
            }
            #pragma unroll
            for (int ni = 0; ni < 4; ++ni) {
                const int n = wn + ni * 8 + g;
                bf[ni][0] = f2tf32(Bs[s][n][kk + t]);
                bf[ni][1] = f2tf32(Bs[s][n][kk + t + 4]);
            }
            #pragma unroll
            for (int mi = 0; mi < 4; ++mi)
                #pragma unroll
                for (int ni = 0; ni < 4; ++ni)
                    mma_tf32(acc[mi][ni], af[mi], bf[ni]);
        }
    }

    #pragma unroll
    for (int mi = 0; mi < 4; ++mi)
        #pragma unroll
        for (int ni = 0; ni < 4; ++ni) {
            const int m = bm + wm + mi * 16 + g;
            const int n = bn + wn + ni * 8 + 2 * t;
            float2 v0 = make_float2(acc[mi][ni][0], acc[mi][ni][1]);
            float2 v1 = make_float2(acc[mi][ni][2], acc[mi][ni][3]);
            *(float2*)&g_mul[(size_t)m * TWO_N + n]       = v0;
            *(float2*)&g_mul[(size_t)(m + 8) * TWO_N + n] = v1;
        }
}

// ============================================================================
// Fused per-row URNN, mixed-radix 8*8*8*4 register FFT (proven R7 version)
// ============================================================================
#define RT  256
#define SW(i) ((i) ^ (((i) >> 3) & 31))
#define FPI 3.14159265358979f

__device__ __forceinline__ void bfly(float& ar, float& ai, float& br, float& bi,
                                     float wr, float wi)
{
    const float tr = wr * br - wi * bi;
    const float ti = wr * bi + wi * br;
    br = ar - tr; bi = ai - ti;
    ar = ar + tr; ai = ai + ti;
}

__device__ __forceinline__ void radix8(float* xr, float* xi, float phi, float sgn)
{
    float c1, s1, c2, s2, c3, s3;
    __sincosf(phi,          &s1, &c1);
    __sincosf(phi * 0.50f,  &s2, &c2);
    __sincosf(phi * 0.25f,  &s3, &c3);
    bfly(xr[0], xi[0], xr[1], xi[1], c1, s1);
    bfly(xr[2], xi[2], xr[3], xi[3], c1, s1);
    bfly(xr[4], xi[4], xr[5], xi[5], c1, s1);
    bfly(xr[6], xi[6], xr[7], xi[7], c1, s1);
    const float wbr = -sgn * s2, wbi = sgn * c2;
    bfly(xr[0], xi[0], xr[2], xi[2], c2, s2);
    bfly(xr[1], xi[1], xr[3], xi[3], wbr, wbi);
    bfly(xr[4], xi[4], xr[6], xi[6], c2, s2);
    bfly(xr[5], xi[5], xr[7], xi[7], wbr, wbi);
    const float h = 0.70710678118f;
    const float w1r = h * (c3 - sgn * s3), w1i = h * (sgn * c3 + s3);
    const float w2r = -sgn * s3,           w2i = sgn * c3;
    const float w3r = -h * (c3 + sgn * s3), w3i = h * (sgn * c3 - s3);
    bfly(xr[0], xi[0], xr[4], xi[4], c3, s3);
    bfly(xr[1], xi[1], xr[5], xi[5], w1r, w1i);
    bfly(xr[2], xi[2], xr[6], xi[6], w2r, w2i);
    bfly(xr[3], xi[3], xr[7], xi[7], w3r, w3i);
}

__device__ __forceinline__ void radix4(float* xr, float* xi, float alpha, float sgn)
{
    float c1, s1, c2, s2;
    __sincosf(alpha,         &s1, &c1);
    __sincosf(alpha * 0.5f,  &s2, &c2);
    bfly(xr[0], xi[0], xr[1], xi[1], c1, s1);
    bfly(xr[2], xi[2], xr[3], xi[3], c1, s1);
    const float wbr = -sgn * s2, wbi = sgn * c2;
    bfly(xr[0], xi[0], xr[2], xi[2], c2, s2);
    bfly(xr[1], xi[1], xr[3], xi[3], wbr, wbi);
}

__device__ __forceinline__ void fft2048_r8(float* __restrict__ sre, float* __restrict__ sim,
                                           int tid, float sgn, float* zr, float* zi)
{
    float xr[8], xi[8];
    const int rT = (int)(__brev((unsigned)tid) >> 24);   // rev8(tid)
    #pragma unroll
    for (int e = 0; e < 8; ++e) {
        const int r3 = ((e & 1) << 2) | (e & 2) | ((e & 4) >> 2);   // rev3(e)
        const int a = SW((r3 << 8) | rT);
        xr[e] = sre[a]; xi[e] = sim[a];
    }
    __syncthreads();
    radix8(xr, xi, 0.0f, sgn);
    #pragma unroll
    for (int e = 0; e < 8; ++e) {
        const int a = SW(8 * tid + e);
        sre[a] = xr[e]; sim[a] = xi[e];
    }
    __syncthreads();
    {
        const int low = tid & 7, base = ((tid >> 3) << 6) + low;
        #pragma unroll
        for (int e = 0; e < 8; ++e) { const int a = SW(base + 8 * e); xr[e] = sre[a]; xi[e] = sim[a]; }
        radix8(xr, xi, sgn * FPI * (float)low * 0.125f, sgn);
        #pragma unroll
        for (int e = 0; e < 8; ++e) { const int a = SW(base + 8 * e); sre[a] = xr[e]; sim[a] = xi[e]; }
    }
    __syncthreads();
    {
        const int low = tid & 63, base = ((tid >> 6) << 9) + low;
        #pragma unroll
        for (int e = 0; e < 8; ++e) { const int a = SW(base + 64 * e); xr[e] = sre[a]; xi[e] = sim[a]; }
        radix8(xr, xi, sgn * FPI * (float)low * (1.0f / 64.0f), sgn);
        #pragma unroll
        for (int e = 0; e < 8; ++e) { const int a = SW(base + 64 * e); sre[a] = xr[e]; sim[a] = xi[e]; }
    }
    __syncthreads();
    #pragma unroll
    for (int r = 0; r < 2; ++r) {
        const int low = tid + 256 * r;
        float br[4], bi[4];
        #pragma unroll
        for (int e = 0; e < 4; ++e) { const int a = SW(low + 512 * e); br[e] = sre[a]; bi[e] = sim[a]; }
        radix4(br, bi, sgn * FPI * (float)low * (1.0f / 512.0f), sgn);
        #pragma unroll
        for (int e = 0; e < 4; ++e) { zr[r * 4 + e] = br[e]; zi[r * 4 + e] = bi[e]; }
    }
}

__device__ __forceinline__ void reflect_regs(float* zr, float* zi,
    const float* __restrict__ vre, const float* __restrict__ vim,
    float* red, int tid)
{
    float sq = 0.f, dr = 0.f, di = 0.f;
    #pragma unroll
    for (int r = 0; r < 2; ++r)
        #pragma unroll
        for (int e = 0; e < 4; ++e) {
            const int i = tid + 256 * r + 512 * e;
            const float vr = vre[i], vi = vim[i];
            const float a = zr[r * 4 + e], b = zi[r * 4 + e];
            sq += vr * vr + vi * vi;
            dr += a * vr + b * vi;
            di += b * vr - a * vi;
        }
    #pragma unroll
    for (int off = 16; off > 0; off >>= 1) {
        sq += __shfl_down_sync(0xffffffffu, sq, off);
        dr += __shfl_down_sync(0xffffffffu, dr, off);
        di += __shfl_down_sync(0xffffffffu, di, off);
    }
    const int warp = tid >> 5, lane = tid & 31;
    if (lane == 0) { red[warp] = sq; red[8 + warp] = dr; red[16 + warp] = di; }
    __syncthreads();
    if (tid == 0) {
        float a = 0.f, b = 0.f, c = 0.f;
        #pragma unroll
        for (int w = 0; w < 8; ++w) { a += red[w]; b += red[8 + w]; c += red[16 + w]; }
        const float f = 2.0f / a;
        red[24] = f * b;
        red[25] = f * c;
    }
    __syncthreads();
    const float cr = red[24], ci = red[25];
    #pragma unroll
    for (int r = 0; r < 2; ++r)
        #pragma unroll
        for (int e = 0; e < 4; ++e) {
            const int i = tid + 256 * r + 512 * e;
            const float vr = vre[i], vi = vim[i];
            zr[r * 4 + e] -= cr * vr - ci * vi;
            zi[r * 4 + e] -= cr * vi + ci * vr;
        }
}

__global__ __launch_bounds__(RT, 2) void urnn_row_kernel(
    const float* __restrict__ state,
    const float* __restrict__ b_h,
    const float* __restrict__ d1, const float* __restrict__ r1re, const float* __restrict__ r1im,
    const float* __restrict__ d2, const float* __restrict__ r2re, const float* __restrict__ r2im,
    const float* __restrict__ d3, const int* __restrict__ perm,
    float* __restrict__ out)
{
    __shared__ float sre[NDIM], sim[NDIM];
    __shared__ float red[32];

    const int tid = threadIdx.x;
    const size_t row = (size_t)blockIdx.x * TWO_N;
    const float* st   = state + row;
    const float* mrow = g_mul + row;
    float*       orow = out + row;

    float zr[8], zi[8];

    #pragma unroll
    for (int j = 0; j < 8; ++j) {
        const int i = tid + j * RT;
        const float re = st[i], im = st[i + NDIM];
        float c, s;
        __sincosf(d1[i], &s, &c);
        const int a = SW(i);
        sre[a] = c * re - s * im;
        sim[a] = c * im + s * re;
    }
    __syncthreads();

    fft2048_r8(sre, sim, tid, -1.0f, zr, zi);
    reflect_regs(zr, zi, r1re, r1im, red, tid);

    #pragma unroll
    for (int r = 0; r < 2; ++r)
        #pragma unroll
        for (int e = 0; e < 4; ++e) {
            const int i = tid + 256 * r + 512 * e;
            const int a = SW(i);
            sre[a] = zr[r * 4 + e]; sim[a] = zi[r * 4 + e];
        }
    __syncthreads();

    {
        float tre[8], tim[8];
        #pragma unroll
        for (int j = 0; j < 8; ++j) {
            const int i = tid + j * RT;
            const int p = perm[i];
            const int a = SW(p);
            tre[j] = sre[a]; tim[j] = sim[a];
        }
        __syncthreads();
        #pragma unroll
        for (int j = 0; j < 8; ++j) {
            const int i = tid + j * RT;
            float c, s;
            __sincosf(d2[i], &s, &c);
            const int a = SW(i);
            sre[a] = c * tre[j] - s * tim[j];
            sim[a] = c * tim[j] + s * tre[j];
        }
        __syncthreads();
    }

    fft2048_r8(sre, sim, tid, +1.0f, zr, zi);
    reflect_regs(zr, zi, r2re, r2im, red, tid);

    const float invn = 1.0f / (float)NDIM;
    #pragma unroll
    for (int r = 0; r < 2; ++r)
        #pragma unroll
        for (int e = 0; e < 4; ++e) {
            const int i = tid + 256 * r + 512 * e;
            const float zr0 = zr[r * 4 + e], zi0 = zi[r * 4 + e];
            float c, s;
            __sincosf(d3[i], &s, &c);
            const float zzr = (c * zr0 - s * zi0) * invn;
            const float zzi = (c * zi0 + s * zr0) * invn;
            const float pr = mrow[i] + zzr;
            const float pi = mrow[i + NDIM] + zzi;
            const float nrm = sqrtf(pr * pr + pi * pi);
            const float sc = fmaxf(nrm + b_h[i], 0.0f) / (nrm + 1e-6f);
            orow[i]        = pr * sc;
            orow[i + NDIM] = pi * sc;
        }
}

// ============================================================================
extern "C" void kernel_launch(void* const* d_in, const int* in_sizes, int n_in,
                              void* d_out, int out_size)
{
    const float* inputs = (const float*)d_in[0];
    const float* state  = (const float*)d_in[1];
    const float* w_ih   = (const float*)d_in[2];
    const float* b_h    = (const float*)d_in[3];
    const float* d1     = (const float*)d_in[4];
    const float* r1re   = (const float*)d_in[5];
    const float* r1im   = (const float*)d_in[6];
    const float* d2     = (const float*)d_in[7];
    const float* r2re   = (const float*)d_in[8];
    const float* r2im   = (const float*)d_in[9];
    const float* d3     = (const float*)d_in[10];
    const int*   perm   = (const int*)d_in[11];
    float* out = (float*)d_out;

    dim3 ggrid(TWO_N / BN, BATCH / BM);       // (32, 64)
    gemm_tf32_kernel<<<ggrid, 256>>>(inputs, w_ih);
    urnn_row_kernel<<<BATCH, RT>>>(state, b_h, d1, r1re, r1im,
                                   d2, r2re, r2im, d3, perm, out);
}